// round 16
// baseline (speedup 1.0000x reference)
#include <cuda_runtime.h>
#include <cuda_fp16.h>
#include <cstdint>

#define DDIM   128
#define KPROTO 1024
typedef unsigned int u32;
typedef unsigned long long ull;

// Static device storage (no allocation).
__device__ uint4 g_B [64 * 8 * 32];     // 256 KB: B-hi frags [nbpair][ks][lane] = {b0E,b1E,b0O,b1O}
__device__ float g_la [KPROTO];         // -10*log2e*alpha - c*pi^2/4

// ---------------- helpers ----------------
__device__ __forceinline__ u32 pack_h2(float a, float b) {
    __half2 t;
    t.x = __float2half_rn(a);
    t.y = __float2half_rn(b);
    return *reinterpret_cast<u32*>(&t);
}
__device__ __forceinline__ ull pack2(float lo, float hi) {
    ull r; asm("mov.b64 %0, {%1, %2};" : "=l"(r) : "f"(lo), "f"(hi)); return r;
}
__device__ __forceinline__ void unpack2(ull v, float& lo, float& hi) {
    asm("mov.b64 {%0, %1}, %2;" : "=f"(lo), "=f"(hi) : "l"(v));
}
__device__ __forceinline__ ull fma2(ull a, ull b, ull c) {
    ull d; asm("fma.rn.f32x2 %0, %1, %2, %3;" : "=l"(d) : "l"(a), "l"(b), "l"(c)); return d;
}
__device__ __forceinline__ ull mul2(ull a, ull b) {
    ull d; asm("mul.rn.f32x2 %0, %1, %2;" : "=l"(d) : "l"(a), "l"(b)); return d;
}
__device__ __forceinline__ float ex2(float x) {
    float r; asm("ex2.approx.f32 %0, %1;" : "=f"(r) : "f"(x)); return r;
}
__device__ __forceinline__ void mma16816h(float& d0, float& d1, float& d2, float& d3,
                                          u32 a0, u32 a1, u32 a2, u32 a3,
                                          u32 b0, u32 b1) {
    asm volatile(
        "mma.sync.aligned.m16n8k16.row.col.f32.f16.f16.f32 "
        "{%0,%1,%2,%3},{%4,%5,%6,%7},{%8,%9},{%0,%1,%2,%3};"
        : "+f"(d0), "+f"(d1), "+f"(d2), "+f"(d3)
        : "r"(a0), "r"(a1), "r"(a2), "r"(a3), "r"(b0), "r"(b1));
}

// ---------------- fused prep: per-block column norms + B fragment packing ----------------
__global__ void prepFused(const float* __restrict__ mus, const float* __restrict__ alphas) {
    __shared__ float s_part[256];
    __shared__ float s_inv[16];

    const int tid = threadIdx.x;
    const int np  = blockIdx.x;
    const int n0  = np * 16;

    {
        int c = tid & 15, p = tid >> 4;
        float s = 0.0f;
#pragma unroll
        for (int i = 0; i < 8; i++) {
            float v = mus[(p * 8 + i) * KPROTO + n0 + c];
            s = fmaf(v, v, s);
        }
        s_part[tid] = s;
    }
    __syncthreads();
    if (tid < 16) {
        float t = 0.0f;
#pragma unroll
        for (int j = 0; j < 16; j++) t += s_part[j * 16 + tid];
        s_inv[tid] = rsqrtf(t);
        g_la[n0 + tid] = fmaf(-14.4269504088896340f, alphas[n0 + tid], -17.7985387f);
    }
    __syncthreads();

    {
        int lane = tid & 31;
        int ks   = tid >> 5;
        int g    = lane >> 2;
        int t4   = lane & 3;
        int k0   = ks * 16 + 2 * t4;
        int nE   = n0 + g;
        int nO   = nE + 8;
        float iE = s_inv[g], iO = s_inv[g + 8];
        float e0 = mus[(k0 + 0) * KPROTO + nE] * iE;
        float e1 = mus[(k0 + 1) * KPROTO + nE] * iE;
        float e2 = mus[(k0 + 8) * KPROTO + nE] * iE;
        float e3 = mus[(k0 + 9) * KPROTO + nE] * iE;
        float o0 = mus[(k0 + 0) * KPROTO + nO] * iO;
        float o1 = mus[(k0 + 1) * KPROTO + nO] * iO;
        float o2 = mus[(k0 + 8) * KPROTO + nO] * iO;
        float o3 = mus[(k0 + 9) * KPROTO + nO] * iO;
        uint4 o;
        o.x = pack_h2(e0, e1);
        o.y = pack_h2(e2, e3);
        o.z = pack_h2(o0, o1);
        o.w = pack_h2(o2, o3);
        g_B[(np * 8 + ks) * 32 + lane] = o;
    }
}

// ---------------- main: 64 rows/block, both warps sweep ALL 64 nb-pairs ----------------
// Block = 64 thr = 2 warps; warp h owns rows [blk*64 + h*32, +32) (2 strips).
// Both warps iterate nb-pairs 0..63 in the same order -> shared B stream hits L1.
// Grid = 1024 blocks <= 148x8 slots -> single full wave. Warp-complete sums,
// direct store (no smem reduction).
__global__ __launch_bounds__(64, 8)
void main_kernel(const float* __restrict__ xs, float* __restrict__ out) {
    const int tid  = threadIdx.x;
    const int half = tid >> 5;             // warp id
    const int lane = tid & 31;
    const int g    = lane >> 2;
    const int t4   = lane & 3;
    const int row0 = blockIdx.x * 64 + half * 32 + g;   // strip0 rows: row0, row0+8
    const int row1 = row0 + 16;                          // strip1 rows: row1, row1+8

    // A fragments for both strips: convert 32 xs rows to fp16 in registers
    uint4 A0[8], A1[8];
    {
        const float* x00 = xs + (size_t)row0 * DDIM;
        const float* x01 = xs + (size_t)(row0 + 8) * DDIM;
        const float* x10 = xs + (size_t)row1 * DDIM;
        const float* x11 = xs + (size_t)(row1 + 8) * DDIM;
#pragma unroll
        for (int ks = 0; ks < 8; ks++) {
            int c0 = ks * 16 + 2 * t4;
            float2 p00 = *(const float2*)(x00 + c0);
            float2 p01 = *(const float2*)(x00 + c0 + 8);
            float2 p10 = *(const float2*)(x01 + c0);
            float2 p11 = *(const float2*)(x01 + c0 + 8);
            A0[ks].x = pack_h2(p00.x, p00.y);
            A0[ks].y = pack_h2(p10.x, p10.y);
            A0[ks].z = pack_h2(p01.x, p01.y);
            A0[ks].w = pack_h2(p11.x, p11.y);
            float2 q00 = *(const float2*)(x10 + c0);
            float2 q01 = *(const float2*)(x10 + c0 + 8);
            float2 q10 = *(const float2*)(x11 + c0);
            float2 q11 = *(const float2*)(x11 + c0 + 8);
            A1[ks].x = pack_h2(q00.x, q00.y);
            A1[ks].y = pack_h2(q10.x, q10.y);
            A1[ks].z = pack_h2(q01.x, q01.y);
            A1[ks].w = pack_h2(q11.x, q11.y);
        }
    }

    // asin Taylor (odd, deg 9) + exponent-fold constants (packed)
    const ull CA1  = pack2(0.16666667f,  0.16666667f);
    const ull CA2  = pack2(0.075f,       0.075f);
    const ull CA3  = pack2(0.044642857f, 0.044642857f);
    const ull CA4  = pack2(0.030381944f, 0.030381944f);
    const ull NEGC = pack2(-7.2134752f,  -7.2134752f);
    const ull CPI  = pack2(22.6618023f,  22.6618023f);

    auto tpair = [&](ull x2, ull la2) -> float {
        ull u  = mul2(x2, x2);
        ull q  = fma2(CA4, u, CA3);
        q = fma2(q, u, CA2);
        q = fma2(q, u, CA1);
        ull xu = mul2(x2, u);
        ull p  = fma2(xu, q, x2);     // asin(x)
        ull t  = fma2(p, NEGC, CPI);
        ull z  = fma2(p, t, la2);     // -c*p^2 + c*pi*p + la'
        float z0, z1; unpack2(z, z0, z1);
        return ex2(z0) + ex2(z1);
    };

    float s0 = 0.0f, s1 = 0.0f, s2 = 0.0f, s3 = 0.0f;
    const float2* la_p = (const float2*)g_la;
    ull ipp[8];   // strip0: [E g | E g8 | O g | O g8], strip1: +4

    auto epi0 = [&](int itp) {
        float2 laE = la_p[itp * 8 + t4];
        float2 laO = la_p[itp * 8 + 4 + t4];
        ull laE2 = pack2(laE.x, laE.y), laO2 = pack2(laO.x, laO.y);
        s0 += tpair(ipp[0], laE2) + tpair(ipp[2], laO2);
        s1 += tpair(ipp[1], laE2) + tpair(ipp[3], laO2);
    };
    auto epi1 = [&](int itp) {
        float2 laE = la_p[itp * 8 + t4];
        float2 laO = la_p[itp * 8 + 4 + t4];
        ull laE2 = pack2(laE.x, laE.y), laO2 = pack2(laO.x, laO.y);
        s2 += tpair(ipp[4], laE2) + tpair(ipp[6], laO2);
        s3 += tpair(ipp[5], laE2) + tpair(ipp[7], laO2);
    };

    auto body = [&](int it, bool epi) {
        const uint4* pB = g_B + it * 256 + lane;
        uint4 b0 = pB[0], b1 = pB[32], b2 = pB[64], b3 = pB[96];

        float E00=0,E01=0,E02=0,E03=0;   // strip0 E
        float O00=0,O01=0,O02=0,O03=0;   // strip0 O
        float E10=0,E11=0,E12=0,E13=0;   // strip1 E
        float O10=0,O11=0,O12=0,O13=0;   // strip1 O

        // ks 0..3, 4 chains
        mma16816h(E00,E01,E02,E03, A0[0].x,A0[0].y,A0[0].z,A0[0].w, b0.x,b0.y);
        mma16816h(O00,O01,O02,O03, A0[0].x,A0[0].y,A0[0].z,A0[0].w, b0.z,b0.w);
        mma16816h(E10,E11,E12,E13, A1[0].x,A1[0].y,A1[0].z,A1[0].w, b0.x,b0.y);
        mma16816h(O10,O11,O12,O13, A1[0].x,A1[0].y,A1[0].z,A1[0].w, b0.z,b0.w);
        mma16816h(E00,E01,E02,E03, A0[1].x,A0[1].y,A0[1].z,A0[1].w, b1.x,b1.y);
        mma16816h(O00,O01,O02,O03, A0[1].x,A0[1].y,A0[1].z,A0[1].w, b1.z,b1.w);
        mma16816h(E10,E11,E12,E13, A1[1].x,A1[1].y,A1[1].z,A1[1].w, b1.x,b1.y);
        mma16816h(O10,O11,O12,O13, A1[1].x,A1[1].y,A1[1].z,A1[1].w, b1.z,b1.w);
        mma16816h(E00,E01,E02,E03, A0[2].x,A0[2].y,A0[2].z,A0[2].w, b2.x,b2.y);
        mma16816h(O00,O01,O02,O03, A0[2].x,A0[2].y,A0[2].z,A0[2].w, b2.z,b2.w);
        mma16816h(E10,E11,E12,E13, A1[2].x,A1[2].y,A1[2].z,A1[2].w, b2.x,b2.y);
        mma16816h(O10,O11,O12,O13, A1[2].x,A1[2].y,A1[2].z,A1[2].w, b2.z,b2.w);
        mma16816h(E00,E01,E02,E03, A0[3].x,A0[3].y,A0[3].z,A0[3].w, b3.x,b3.y);
        mma16816h(O00,O01,O02,O03, A0[3].x,A0[3].y,A0[3].z,A0[3].w, b3.z,b3.w);
        mma16816h(E10,E11,E12,E13, A1[3].x,A1[3].y,A1[3].z,A1[3].w, b3.x,b3.y);
        mma16816h(O10,O11,O12,O13, A1[3].x,A1[3].y,A1[3].z,A1[3].w, b3.z,b3.w);

        // back-half loads; covered by epi0 + remaining MMAs
        uint4 b4 = pB[128], b5 = pB[160], b6 = pB[192], b7 = pB[224];

        if (epi) epi0(it - 1);

        // ks 4..7
        mma16816h(E00,E01,E02,E03, A0[4].x,A0[4].y,A0[4].z,A0[4].w, b4.x,b4.y);
        mma16816h(O00,O01,O02,O03, A0[4].x,A0[4].y,A0[4].z,A0[4].w, b4.z,b4.w);
        mma16816h(E10,E11,E12,E13, A1[4].x,A1[4].y,A1[4].z,A1[4].w, b4.x,b4.y);
        mma16816h(O10,O11,O12,O13, A1[4].x,A1[4].y,A1[4].z,A1[4].w, b4.z,b4.w);
        mma16816h(E00,E01,E02,E03, A0[5].x,A0[5].y,A0[5].z,A0[5].w, b5.x,b5.y);
        mma16816h(O00,O01,O02,O03, A0[5].x,A0[5].y,A0[5].z,A0[5].w, b5.z,b5.w);
        mma16816h(E10,E11,E12,E13, A1[5].x,A1[5].y,A1[5].z,A1[5].w, b5.x,b5.y);
        mma16816h(O10,O11,O12,O13, A1[5].x,A1[5].y,A1[5].z,A1[5].w, b5.z,b5.w);
        mma16816h(E00,E01,E02,E03, A0[6].x,A0[6].y,A0[6].z,A0[6].w, b6.x,b6.y);
        mma16816h(O00,O01,O02,O03, A0[6].x,A0[6].y,A0[6].z,A0[6].w, b6.z,b6.w);
        mma16816h(E10,E11,E12,E13, A1[6].x,A1[6].y,A1[6].z,A1[6].w, b6.x,b6.y);
        mma16816h(O10,O11,O12,O13, A1[6].x,A1[6].y,A1[6].z,A1[6].w, b6.z,b6.w);
        mma16816h(E00,E01,E02,E03, A0[7].x,A0[7].y,A0[7].z,A0[7].w, b7.x,b7.y);
        mma16816h(O00,O01,O02,O03, A0[7].x,A0[7].y,A0[7].z,A0[7].w, b7.z,b7.w);
        mma16816h(E10,E11,E12,E13, A1[7].x,A1[7].y,A1[7].z,A1[7].w, b7.x,b7.y);
        mma16816h(O10,O11,O12,O13, A1[7].x,A1[7].y,A1[7].z,A1[7].w, b7.z,b7.w);

        if (epi) epi1(it - 1);

        ipp[0] = pack2(E00, E01);  ipp[1] = pack2(E02, E03);
        ipp[2] = pack2(O00, O01);  ipp[3] = pack2(O02, O03);
        ipp[4] = pack2(E10, E11);  ipp[5] = pack2(E12, E13);
        ipp[6] = pack2(O10, O11);  ipp[7] = pack2(O12, O13);
    };

    body(0, false);                      // peeled prologue
#pragma unroll 1
    for (int it = 1; it < 64; it++) {
        if ((it & 7) == 0) __syncthreads();   // keep the 2 warps' B streams converged
        body(it, true);
    }
    epi0(63);                            // drain
    epi1(63);

    // reduce across the 4 lanes sharing the same rows (t4 = 0..3)
    s0 += __shfl_xor_sync(0xffffffffu, s0, 1);
    s0 += __shfl_xor_sync(0xffffffffu, s0, 2);
    s1 += __shfl_xor_sync(0xffffffffu, s1, 1);
    s1 += __shfl_xor_sync(0xffffffffu, s1, 2);
    s2 += __shfl_xor_sync(0xffffffffu, s2, 1);
    s2 += __shfl_xor_sync(0xffffffffu, s2, 2);
    s3 += __shfl_xor_sync(0xffffffffu, s3, 1);
    s3 += __shfl_xor_sync(0xffffffffu, s3, 2);

    if (t4 == 0) {
        out[row0]      = 0.1f * log1pf(1.0f / s0);
        out[row0 + 8]  = 0.1f * log1pf(1.0f / s1);
        out[row1]      = 0.1f * log1pf(1.0f / s2);
        out[row1 + 8]  = 0.1f * log1pf(1.0f / s3);
    }
}

// ---------------- launch ----------------
extern "C" void kernel_launch(void* const* d_in, const int* in_sizes, int n_in,
                              void* d_out, int out_size) {
    const float* xs     = (const float*)d_in[0];
    const float* mus    = (const float*)d_in[1];
    const float* alphas = (const float*)d_in[2];
    float* out = (float*)d_out;

    int B = in_sizes[0] / DDIM;    // 65536

    prepFused<<<64, 256>>>(mus, alphas);      // one prep launch
    main_kernel<<<B / 64, 64>>>(xs, out);     // 1024 blocks x 2 warps — single wave
}